// round 1
// baseline (speedup 1.0000x reference)
#include <cuda_runtime.h>

#define TPB   128
#define NR    32768
#define DD    64
#define LL    63
#define HH    8
#define PP    14
#define KB    5
#define BBf   5.0f
#define MINW  0.001f
#define MINH  0.001f
#define MIND  0.001f
#define XST   65   // padded smem stride: (tid*65 + j) % 32 = (tid+j)%32 -> conflict-free

__device__ __forceinline__ float tanh_acc(float x){
    // accurate-enough tanh: 1 - 2/(exp(2x)+1); safe at +-inf ranges
    float t = __expf(2.0f * x);
    return 1.0f - __fdividef(2.0f, t + 1.0f);
}

__device__ __forceinline__ void rqs_eval(const float* p, float xf, float& z, float& ldout)
{
    bool inside = (xf >= -BBf) && (xf <= BBf);
    float xc = fminf(fmaxf(xf, -BBf), BBf);

    float ew[KB], eh[KB];
    float sw = 0.f, sh = 0.f;
#pragma unroll
    for (int k = 0; k < KB; k++){ ew[k] = __expf(p[k]);      sw += ew[k]; }
#pragma unroll
    for (int k = 0; k < KB; k++){ eh[k] = __expf(p[KB + k]); sh += eh[k]; }
    float aW = __fdividef(1.0f - KB * MINW, sw);
    float aH = __fdividef(1.0f - KB * MINH, sh);

    // sequential scan over bins; select bin = last k with cumw[k] <= xc
    float curw = -BBf, curh = -BBf;
    float icw = -BBf, ich = -BBf, ibw = 1.f, ih = 1.f;
    float duL = 0.f, duR = 0.f;
    bool firstbin = true, lastbin = false;
#pragma unroll
    for (int k = 0; k < KB; k++){
        float nw = (k == KB-1) ? BBf : curw + 2.0f * BBf * (MINW + aW * ew[k]);
        float nh = (k == KB-1) ? BBf : curh + 2.0f * BBf * (MINH + aH * eh[k]);
        bool c = (k == 0) || (xc >= curw);
        if (c){
            icw = curw; ich = curh; ibw = nw - curw; ih = nh - curh;
            firstbin = (k == 0); lastbin = (k == KB-1);
            duL = (k == 0)      ? 0.f : p[2*KB + k - 1];
            duR = (k == KB-1)   ? 0.f : p[2*KB + k];
        }
        curw = nw; curh = nh;
    }
    // boundary derivatives are exactly 1.0 (MIN_D + softplus(log(exp(1-MIN_D)-1)))
    float idv   = firstbin ? 1.0f : (MIND + __logf(1.0f + __expf(duL)));
    float idvp1 = lastbin  ? 1.0f : (MIND + __logf(1.0f + __expf(duR)));

    float rbw   = __fdividef(1.0f, ibw);
    float theta = (xc - icw) * rbw;
    float idl   = ih * rbw;
    float tmt   = theta * (1.0f - theta);
    float th2   = theta * theta;
    float num   = ih * (idl * th2 + idv * tmt);
    float den   = idl + (idv + idvp1 - 2.0f * idl) * tmt;
    float outv  = ich + __fdividef(num, den);
    float omt   = 1.0f - theta;
    float dnum  = idl * idl * (idvp1 * th2 + 2.0f * idl * tmt + idv * omt * omt);
    float lv    = __logf(dnum) - 2.0f * __logf(den);

    z     = inside ? outv : xf;
    ldout = inside ? lv   : 0.0f;
}

__global__ __launch_bounds__(TPB)
void nsf_ar_kernel(const float* __restrict__ x,
                   const float* __restrict__ initp,
                   const float* __restrict__ W1,
                   const float* __restrict__ b1,
                   const float* __restrict__ W2,
                   const float* __restrict__ b2,
                   const float* __restrict__ W3,
                   const float* __restrict__ b3,
                   float* __restrict__ out)
{
    __shared__ __align__(16) float xsh[TPB * XST];
    __shared__ __align__(16) float w1s[LL * HH];    // up to 504
    __shared__ __align__(16) float w2s[HH * HH];    // 64
    __shared__ __align__(16) float w3s[HH * 16];    // padded to 16 cols
    __shared__ __align__(16) float b1s[HH], b2s[HH], b3s[16];
    __shared__ float redbuf[4];

    const int tid  = threadIdx.x;
    const int row0 = blockIdx.x * TPB;
    const int row  = row0 + tid;

    // stage x tile (coalesced global read, padded smem write)
    for (int i = tid; i < TPB * DD; i += TPB){
        int r = i / DD, c = i % DD;
        xsh[r * XST + c] = x[(row0 + r) * DD + c];
    }
    __syncthreads();

    const float* xr = &xsh[tid * XST];
    float* out2 = out + (size_t)NR * DD;

    // ---------------- dim 0: init_param ----------------
    {
        float p[PP];
#pragma unroll
        for (int c = 0; c < PP; c++) p[c] = initp[c];
        float z, ld;
        rqs_eval(p, xr[0], z, ld);
        out[row] = z;
#pragma unroll
        for (int o = 16; o > 0; o >>= 1) ld += __shfl_down_sync(0xffffffffu, ld, o);
        if ((tid & 31) == 0) redbuf[tid >> 5] = ld;
        __syncthreads();
        if (tid < 2) out2[blockIdx.x * 2 + tid] = redbuf[2*tid] + redbuf[2*tid + 1];
    }

    // ---------------- dims 1..63: MLP + spline ----------------
    for (int dim = 1; dim < DD; dim++){
        const int l = dim - 1;

        // stage this dim's weights into smem
        const int n1 = (l + 1) * HH;
        for (int t = tid; t < n1; t += TPB)       w1s[t] = W1[l * (LL*HH) + t];
        if (tid < HH * HH)                        w2s[tid] = W2[l * (HH*HH) + tid];
        {
            // W3 [8][14] -> padded [8][16]
            for (int t = tid; t < HH * PP; t += TPB){
                int g = t / PP, c = t % PP;
                w3s[g * 16 + c] = W3[l * (HH*PP) + t];
            }
            if (tid >= 112 && tid < 128){
                int u = tid - 112;
                w3s[(u >> 1) * 16 + 14 + (u & 1)] = 0.f;
            }
        }
        if      (tid < HH)            b1s[tid]      = b1[l * HH + tid];
        else if (tid < 2*HH)          b2s[tid - 8]  = b2[l * HH + (tid - 8)];
        else if (tid < 2*HH + PP)     b3s[tid - 16] = b3[l * PP + (tid - 16)];
        else if (tid < 2*HH + 16)     b3s[tid - 16] = 0.f;
        __syncthreads();

        // layer 1: a1[h] = b1 + sum_{j<=l} x[j] * W1[j][h]
        float a1[HH];
#pragma unroll
        for (int h = 0; h < HH; h++) a1[h] = b1s[h];
        for (int j = 0; j <= l; j++){
            float xv = xr[j];
            float4 wa = *reinterpret_cast<const float4*>(&w1s[j * 8]);
            float4 wb = *reinterpret_cast<const float4*>(&w1s[j * 8 + 4]);
            a1[0] += xv * wa.x; a1[1] += xv * wa.y; a1[2] += xv * wa.z; a1[3] += xv * wa.w;
            a1[4] += xv * wb.x; a1[5] += xv * wb.y; a1[6] += xv * wb.z; a1[7] += xv * wb.w;
        }
#pragma unroll
        for (int h = 0; h < HH; h++) a1[h] = tanh_acc(a1[h]);

        // layer 2
        float a2[HH];
#pragma unroll
        for (int g = 0; g < HH; g++) a2[g] = b2s[g];
#pragma unroll
        for (int h = 0; h < HH; h++){
            float hv = a1[h];
            float4 wa = *reinterpret_cast<const float4*>(&w2s[h * 8]);
            float4 wb = *reinterpret_cast<const float4*>(&w2s[h * 8 + 4]);
            a2[0] += hv * wa.x; a2[1] += hv * wa.y; a2[2] += hv * wa.z; a2[3] += hv * wa.w;
            a2[4] += hv * wb.x; a2[5] += hv * wb.y; a2[6] += hv * wb.z; a2[7] += hv * wb.w;
        }
#pragma unroll
        for (int g = 0; g < HH; g++) a2[g] = tanh_acc(a2[g]);

        // layer 3 (padded to 16 outputs; slots 14,15 are zero weights)
        float p[16];
#pragma unroll
        for (int c = 0; c < 16; c++) p[c] = b3s[c];
#pragma unroll
        for (int g = 0; g < HH; g++){
            float gv = a2[g];
            float4 w0 = *reinterpret_cast<const float4*>(&w3s[g * 16 + 0]);
            float4 w1v = *reinterpret_cast<const float4*>(&w3s[g * 16 + 4]);
            float4 w2v = *reinterpret_cast<const float4*>(&w3s[g * 16 + 8]);
            float4 w3v = *reinterpret_cast<const float4*>(&w3s[g * 16 + 12]);
            p[0]  += gv * w0.x;  p[1]  += gv * w0.y;  p[2]  += gv * w0.z;  p[3]  += gv * w0.w;
            p[4]  += gv * w1v.x; p[5]  += gv * w1v.y; p[6]  += gv * w1v.z; p[7]  += gv * w1v.w;
            p[8]  += gv * w2v.x; p[9]  += gv * w2v.y; p[10] += gv * w2v.z; p[11] += gv * w2v.w;
            p[12] += gv * w3v.x; p[13] += gv * w3v.y;
        }

        float z, ld;
        rqs_eval(p, xr[dim], z, ld);
        out[(size_t)dim * NR + row] = z;

        // logdet partial sums: out2[dim*512 + group], group = 64 consecutive rows
#pragma unroll
        for (int o = 16; o > 0; o >>= 1) ld += __shfl_down_sync(0xffffffffu, ld, o);
        if ((tid & 31) == 0) redbuf[tid >> 5] = ld;
        __syncthreads();
        if (tid < 2)
            out2[dim * (NR/64) + blockIdx.x * 2 + tid] = redbuf[2*tid] + redbuf[2*tid + 1];
        // next iteration's weight-stage __syncthreads orders redbuf reuse
    }
}

extern "C" void kernel_launch(void* const* d_in, const int* in_sizes, int n_in,
                              void* d_out, int out_size)
{
    const float* x     = (const float*)d_in[0];
    const float* initp = (const float*)d_in[1];
    const float* W1    = (const float*)d_in[2];
    const float* b1    = (const float*)d_in[3];
    const float* W2    = (const float*)d_in[4];
    const float* b2    = (const float*)d_in[5];
    const float* W3    = (const float*)d_in[6];
    const float* b3    = (const float*)d_in[7];
    float* out = (float*)d_out;

    nsf_ar_kernel<<<NR / TPB, TPB>>>(x, initp, W1, b1, W2, b2, W3, b3, out);
}

// round 6
// speedup vs baseline: 1.7189x; 1.7189x over previous
#include <cuda_runtime.h>

#define TPB   128
#define NR    32768
#define DD    64
#define LL    63
#define HH    8
#define PP    14
#define KB    5
#define NCH   8      // dim chunks; chunk c owns dims ≡ c (mod 8)
#define NRB   (NR / TPB)   // 256 row-blocks
#define BBf   5.0f
#define MINW  0.001f
#define MINH  0.001f
#define MIND  0.001f
#define XST   65   // padded smem stride -> conflict-free column reads

__device__ __forceinline__ float tanh_acc(float x){
    float t = __expf(2.0f * x);
    return 1.0f - __fdividef(2.0f, t + 1.0f);
}

__device__ __forceinline__ void rqs_eval(const float* p, float xf, float& z, float& ldout)
{
    bool inside = (xf >= -BBf) && (xf <= BBf);
    float xc = fminf(fmaxf(xf, -BBf), BBf);

    float ew[KB], eh[KB];
    float sw = 0.f, sh = 0.f;
#pragma unroll
    for (int k = 0; k < KB; k++){ ew[k] = __expf(p[k]);      sw += ew[k]; }
#pragma unroll
    for (int k = 0; k < KB; k++){ eh[k] = __expf(p[KB + k]); sh += eh[k]; }
    float aW = __fdividef(1.0f - KB * MINW, sw);
    float aH = __fdividef(1.0f - KB * MINH, sh);

    float curw = -BBf, curh = -BBf;
    float icw = -BBf, ich = -BBf, ibw = 1.f, ih = 1.f;
    float duL = 0.f, duR = 0.f;
    bool firstbin = true, lastbin = false;
#pragma unroll
    for (int k = 0; k < KB; k++){
        float nw = (k == KB-1) ? BBf : curw + 2.0f * BBf * (MINW + aW * ew[k]);
        float nh = (k == KB-1) ? BBf : curh + 2.0f * BBf * (MINH + aH * eh[k]);
        bool c = (k == 0) || (xc >= curw);
        if (c){
            icw = curw; ich = curh; ibw = nw - curw; ih = nh - curh;
            firstbin = (k == 0); lastbin = (k == KB-1);
            duL = (k == 0)      ? 0.f : p[2*KB + k - 1];
            duR = (k == KB-1)   ? 0.f : p[2*KB + k];
        }
        curw = nw; curh = nh;
    }
    float idv   = firstbin ? 1.0f : (MIND + __logf(1.0f + __expf(duL)));
    float idvp1 = lastbin  ? 1.0f : (MIND + __logf(1.0f + __expf(duR)));

    float rbw   = __fdividef(1.0f, ibw);
    float theta = (xc - icw) * rbw;
    float idl   = ih * rbw;
    float tmt   = theta * (1.0f - theta);
    float th2   = theta * theta;
    float num   = ih * (idl * th2 + idv * tmt);
    float den   = idl + (idv + idvp1 - 2.0f * idl) * tmt;
    float outv  = ich + __fdividef(num, den);
    float omt   = 1.0f - theta;
    float dnum  = idl * idl * (idvp1 * th2 + 2.0f * idl * tmt + idv * omt * omt);
    float lv    = __logf(dnum) - 2.0f * __logf(den);

    z     = inside ? outv : xf;
    ldout = inside ? lv   : 0.0f;
}

__global__ __launch_bounds__(TPB)
void nsf_ar_kernel(const float* __restrict__ x,
                   const float* __restrict__ initp,
                   const float* __restrict__ W1,
                   const float* __restrict__ b1,
                   const float* __restrict__ W2,
                   const float* __restrict__ b2,
                   const float* __restrict__ W3,
                   const float* __restrict__ b3,
                   float* __restrict__ out)
{
    __shared__ __align__(16) float xsh[TPB * XST];
    __shared__ __align__(16) float w1s[LL * HH];
    __shared__ __align__(16) float w2s[HH * HH];
    __shared__ __align__(16) float w3s[HH * 16];
    __shared__ __align__(16) float b1s[HH], b2s[HH], b3s[16];
    __shared__ float redbuf[4];

    const int tid    = threadIdx.x;
    const int bid    = blockIdx.x;          // 0..2047
    const int rowblk = bid & (NRB - 1);     // 0..255
    const int chunk  = bid >> 8;            // 0..7: owns dims ≡ chunk (mod NCH)
    const int row0   = rowblk * TPB;
    const int row    = row0 + tid;

    // stage x tile (coalesced global read, padded smem write)
    for (int i = tid; i < TPB * DD; i += TPB){
        int r = i / DD, c = i % DD;
        xsh[r * XST + c] = x[(row0 + r) * DD + c];
    }
    __syncthreads();

    const float* xr = &xsh[tid * XST];
    float* out2 = out + (size_t)NR * DD;

    for (int dim = chunk; dim < DD; dim += NCH){
        if (dim == 0){
            // ---------------- dim 0: init_param ----------------
            float p[PP];
#pragma unroll
            for (int c = 0; c < PP; c++) p[c] = initp[c];
            float z, ld;
            rqs_eval(p, xr[0], z, ld);
            out[row] = z;
#pragma unroll
            for (int o = 16; o > 0; o >>= 1) ld += __shfl_down_sync(0xffffffffu, ld, o);
            if ((tid & 31) == 0) redbuf[tid >> 5] = ld;
            __syncthreads();
            if (tid < 2) out2[rowblk * 2 + tid] = redbuf[2*tid] + redbuf[2*tid + 1];
            __syncthreads();
            continue;
        }

        const int l = dim - 1;

        // stage this dim's weights into smem
        const int n1 = (l + 1) * HH;
        for (int t = tid; t < n1; t += TPB)       w1s[t] = W1[l * (LL*HH) + t];
        if (tid < HH * HH)                        w2s[tid] = W2[l * (HH*HH) + tid];
        {
            for (int t = tid; t < HH * PP; t += TPB){
                int g = t / PP, c = t % PP;
                w3s[g * 16 + c] = W3[l * (HH*PP) + t];
            }
            if (tid >= 112 && tid < 128){
                int u = tid - 112;
                w3s[(u >> 1) * 16 + 14 + (u & 1)] = 0.f;
            }
        }
        if      (tid < HH)            b1s[tid]      = b1[l * HH + tid];
        else if (tid < 2*HH)          b2s[tid - 8]  = b2[l * HH + (tid - 8)];
        else if (tid < 2*HH + PP)     b3s[tid - 16] = b3[l * PP + (tid - 16)];
        else if (tid < 2*HH + 16)     b3s[tid - 16] = 0.f;
        __syncthreads();

        // layer 1: a1[h] = b1 + sum_{j<=l} x[j] * W1[j][h]
        float a1[HH];
#pragma unroll
        for (int h = 0; h < HH; h++) a1[h] = b1s[h];
        for (int j = 0; j <= l; j++){
            float xv = xr[j];
            float4 wa = *reinterpret_cast<const float4*>(&w1s[j * 8]);
            float4 wb = *reinterpret_cast<const float4*>(&w1s[j * 8 + 4]);
            a1[0] += xv * wa.x; a1[1] += xv * wa.y; a1[2] += xv * wa.z; a1[3] += xv * wa.w;
            a1[4] += xv * wb.x; a1[5] += xv * wb.y; a1[6] += xv * wb.z; a1[7] += xv * wb.w;
        }
#pragma unroll
        for (int h = 0; h < HH; h++) a1[h] = tanh_acc(a1[h]);

        // layer 2
        float a2[HH];
#pragma unroll
        for (int g = 0; g < HH; g++) a2[g] = b2s[g];
#pragma unroll
        for (int h = 0; h < HH; h++){
            float hv = a1[h];
            float4 wa = *reinterpret_cast<const float4*>(&w2s[h * 8]);
            float4 wb = *reinterpret_cast<const float4*>(&w2s[h * 8 + 4]);
            a2[0] += hv * wa.x; a2[1] += hv * wa.y; a2[2] += hv * wa.z; a2[3] += hv * wa.w;
            a2[4] += hv * wb.x; a2[5] += hv * wb.y; a2[6] += hv * wb.z; a2[7] += hv * wb.w;
        }
#pragma unroll
        for (int g = 0; g < HH; g++) a2[g] = tanh_acc(a2[g]);

        // layer 3 (padded to 16 outputs)
        float p[16];
#pragma unroll
        for (int c = 0; c < 16; c++) p[c] = b3s[c];
#pragma unroll
        for (int g = 0; g < HH; g++){
            float gv = a2[g];
            float4 w0 = *reinterpret_cast<const float4*>(&w3s[g * 16 + 0]);
            float4 w1v = *reinterpret_cast<const float4*>(&w3s[g * 16 + 4]);
            float4 w2v = *reinterpret_cast<const float4*>(&w3s[g * 16 + 8]);
            float4 w3v = *reinterpret_cast<const float4*>(&w3s[g * 16 + 12]);
            p[0]  += gv * w0.x;  p[1]  += gv * w0.y;  p[2]  += gv * w0.z;  p[3]  += gv * w0.w;
            p[4]  += gv * w1v.x; p[5]  += gv * w1v.y; p[6]  += gv * w1v.z; p[7]  += gv * w1v.w;
            p[8]  += gv * w2v.x; p[9]  += gv * w2v.y; p[10] += gv * w2v.z; p[11] += gv * w2v.w;
            p[12] += gv * w3v.x; p[13] += gv * w3v.y;
        }

        float z, ld;
        rqs_eval(p, xr[dim], z, ld);
        out[(size_t)dim * NR + row] = z;

#pragma unroll
        for (int o = 16; o > 0; o >>= 1) ld += __shfl_down_sync(0xffffffffu, ld, o);
        if ((tid & 31) == 0) redbuf[tid >> 5] = ld;
        __syncthreads();
        if (tid < 2)
            out2[dim * (NR/64) + rowblk * 2 + tid] = redbuf[2*tid] + redbuf[2*tid + 1];
        __syncthreads();   // redbuf + w*s reuse ordering
    }
}

extern "C" void kernel_launch(void* const* d_in, const int* in_sizes, int n_in,
                              void* d_out, int out_size)
{
    const float* x     = (const float*)d_in[0];
    const float* initp = (const float*)d_in[1];
    const float* W1    = (const float*)d_in[2];
    const float* b1    = (const float*)d_in[3];
    const float* W2    = (const float*)d_in[4];
    const float* b2    = (const float*)d_in[5];
    const float* W3    = (const float*)d_in[6];
    const float* b3    = (const float*)d_in[7];
    float* out = (float*)d_out;

    nsf_ar_kernel<<<NRB * NCH, TPB>>>(x, initp, W1, b1, W2, b2, W3, b3, out);
}

// round 8
// speedup vs baseline: 1.7549x; 1.0210x over previous
#include <cuda_runtime.h>

#define TPB   128
#define NR    32768
#define DD    64
#define LL    63
#define HH    8
#define PP    14
#define KB    5
#define NCH   8            // dim chunks; chunk c owns dims ≡ c (mod 8)
#define NRB   (NR / TPB)   // 256 row-blocks
#define BBf   5.0f
#define MINW  0.001f
#define MINH  0.001f
#define MIND  0.001f
#define XST   65   // padded smem stride -> conflict-free column reads

__device__ __forceinline__ float tanh_fast(float x){
    float y;
    asm("tanh.approx.f32 %0, %1;" : "=f"(y) : "f"(x));
    return y;
}

__device__ __forceinline__ void rqs_eval(const float* p, float xf, float& z, float& ldout)
{
    bool inside = (xf >= -BBf) && (xf <= BBf);
    float xc = fminf(fmaxf(xf, -BBf), BBf);

    float ew[KB], eh[KB];
    float sw = 0.f, sh = 0.f;
#pragma unroll
    for (int k = 0; k < KB; k++){ ew[k] = __expf(p[k]);      sw += ew[k]; }
#pragma unroll
    for (int k = 0; k < KB; k++){ eh[k] = __expf(p[KB + k]); sh += eh[k]; }
    float aW = __fdividef(1.0f - KB * MINW, sw);
    float aH = __fdividef(1.0f - KB * MINH, sh);

    float curw = -BBf, curh = -BBf;
    float icw = -BBf, ich = -BBf, ibw = 1.f, ih = 1.f;
    float duL = 0.f, duR = 0.f;
    bool firstbin = true, lastbin = false;
#pragma unroll
    for (int k = 0; k < KB; k++){
        float nw = (k == KB-1) ? BBf : curw + 2.0f * BBf * (MINW + aW * ew[k]);
        float nh = (k == KB-1) ? BBf : curh + 2.0f * BBf * (MINH + aH * eh[k]);
        bool c = (k == 0) || (xc >= curw);
        if (c){
            icw = curw; ich = curh; ibw = nw - curw; ih = nh - curh;
            firstbin = (k == 0); lastbin = (k == KB-1);
            duL = (k == 0)      ? 0.f : p[2*KB + k - 1];
            duR = (k == KB-1)   ? 0.f : p[2*KB + k];
        }
        curw = nw; curh = nh;
    }
    float idv   = firstbin ? 1.0f : (MIND + __logf(1.0f + __expf(duL)));
    float idvp1 = lastbin  ? 1.0f : (MIND + __logf(1.0f + __expf(duR)));

    float rbw   = __fdividef(1.0f, ibw);
    float theta = (xc - icw) * rbw;
    float idl   = ih * rbw;
    float tmt   = theta * (1.0f - theta);
    float th2   = theta * theta;
    float num   = ih * (idl * th2 + idv * tmt);
    float den   = idl + (idv + idvp1 - 2.0f * idl) * tmt;
    float outv  = ich + __fdividef(num, den);
    float omt   = 1.0f - theta;
    float dnum  = idl * idl * (idvp1 * th2 + 2.0f * idl * tmt + idv * omt * omt);
    float lv    = __logf(dnum) - 2.0f * __logf(den);

    z     = inside ? outv : xf;
    ldout = inside ? lv   : 0.0f;
}

__global__ __launch_bounds__(TPB, 6)
void nsf_ar_kernel(const float* __restrict__ x,
                   const float* __restrict__ initp,
                   const float* __restrict__ W1,
                   const float* __restrict__ b1,
                   const float* __restrict__ W2,
                   const float* __restrict__ b2,
                   const float* __restrict__ W3,
                   const float* __restrict__ b3,
                   float* __restrict__ out)
{
    __shared__ __align__(16) float xsh[TPB * XST];
    __shared__ __align__(16) float w1s[LL * HH];
    __shared__ __align__(16) float w2s[HH * HH];
    __shared__ __align__(16) float w3s[HH * 16];
    __shared__ __align__(16) float b1s[HH], b2s[HH], b3s[16];
    __shared__ float redbuf[4];

    const int tid    = threadIdx.x;
    const int bid    = blockIdx.x;          // 0..2047
    const int rowblk = bid & (NRB - 1);     // 0..255
    const int chunk  = bid >> 8;            // 0..7: owns dims ≡ chunk (mod NCH)
    const int row0   = rowblk * TPB;
    const int row    = row0 + tid;

    // stage x tile (coalesced global read, padded smem write)
    for (int i = tid; i < TPB * DD; i += TPB){
        int r = i / DD, c = i % DD;
        xsh[r * XST + c] = x[(row0 + r) * DD + c];
    }
    __syncthreads();

    const float* xr = &xsh[tid * XST];
    float* out2 = out + (size_t)NR * DD;

    for (int dim = chunk; dim < DD; dim += NCH){
        if (dim == 0){
            // ---------------- dim 0: init_param ----------------
            float p[PP];
#pragma unroll
            for (int c = 0; c < PP; c++) p[c] = initp[c];
            float z, ld;
            rqs_eval(p, xr[0], z, ld);
            out[row] = z;
#pragma unroll
            for (int o = 16; o > 0; o >>= 1) ld += __shfl_down_sync(0xffffffffu, ld, o);
            if ((tid & 31) == 0) redbuf[tid >> 5] = ld;
            __syncthreads();
            if (tid < 2) out2[rowblk * 2 + tid] = redbuf[2*tid] + redbuf[2*tid + 1];
            __syncthreads();
            continue;
        }

        const int l = dim - 1;

        // stage this dim's weights into smem
        const int n1 = (l + 1) * HH;
        for (int t = tid; t < n1; t += TPB)       w1s[t] = W1[l * (LL*HH) + t];
        if (tid < HH * HH)                        w2s[tid] = W2[l * (HH*HH) + tid];
        {
            for (int t = tid; t < HH * PP; t += TPB){
                int g = t / PP, c = t % PP;
                w3s[g * 16 + c] = W3[l * (HH*PP) + t];
            }
            if (tid >= 112 && tid < 128){
                int u = tid - 112;
                w3s[(u >> 1) * 16 + 14 + (u & 1)] = 0.f;
            }
        }
        if      (tid < HH)            b1s[tid]      = b1[l * HH + tid];
        else if (tid < 2*HH)          b2s[tid - 8]  = b2[l * HH + (tid - 8)];
        else if (tid < 2*HH + PP)     b3s[tid - 16] = b3[l * PP + (tid - 16)];
        else if (tid < 2*HH + 16)     b3s[tid - 16] = 0.f;
        __syncthreads();

        // layer 1: a1[h] = b1 + sum_{j<=l} x[j] * W1[j][h]
        float a1[HH];
#pragma unroll
        for (int h = 0; h < HH; h++) a1[h] = b1s[h];
#pragma unroll 4
        for (int j = 0; j <= l; j++){
            float xv = xr[j];
            float4 wa = *reinterpret_cast<const float4*>(&w1s[j * 8]);
            float4 wb = *reinterpret_cast<const float4*>(&w1s[j * 8 + 4]);
            a1[0] += xv * wa.x; a1[1] += xv * wa.y; a1[2] += xv * wa.z; a1[3] += xv * wa.w;
            a1[4] += xv * wb.x; a1[5] += xv * wb.y; a1[6] += xv * wb.z; a1[7] += xv * wb.w;
        }
#pragma unroll
        for (int h = 0; h < HH; h++) a1[h] = tanh_fast(a1[h]);

        // layer 2
        float a2[HH];
#pragma unroll
        for (int g = 0; g < HH; g++) a2[g] = b2s[g];
#pragma unroll
        for (int h = 0; h < HH; h++){
            float hv = a1[h];
            float4 wa = *reinterpret_cast<const float4*>(&w2s[h * 8]);
            float4 wb = *reinterpret_cast<const float4*>(&w2s[h * 8 + 4]);
            a2[0] += hv * wa.x; a2[1] += hv * wa.y; a2[2] += hv * wa.z; a2[3] += hv * wa.w;
            a2[4] += hv * wb.x; a2[5] += hv * wb.y; a2[6] += hv * wb.z; a2[7] += hv * wb.w;
        }
#pragma unroll
        for (int g = 0; g < HH; g++) a2[g] = tanh_fast(a2[g]);

        // layer 3 (padded to 16 outputs)
        float p[16];
#pragma unroll
        for (int c = 0; c < 16; c++) p[c] = b3s[c];
#pragma unroll
        for (int g = 0; g < HH; g++){
            float gv = a2[g];
            float4 w0 = *reinterpret_cast<const float4*>(&w3s[g * 16 + 0]);
            float4 w1v = *reinterpret_cast<const float4*>(&w3s[g * 16 + 4]);
            float4 w2v = *reinterpret_cast<const float4*>(&w3s[g * 16 + 8]);
            float4 w3v = *reinterpret_cast<const float4*>(&w3s[g * 16 + 12]);
            p[0]  += gv * w0.x;  p[1]  += gv * w0.y;  p[2]  += gv * w0.z;  p[3]  += gv * w0.w;
            p[4]  += gv * w1v.x; p[5]  += gv * w1v.y; p[6]  += gv * w1v.z; p[7]  += gv * w1v.w;
            p[8]  += gv * w2v.x; p[9]  += gv * w2v.y; p[10] += gv * w2v.z; p[11] += gv * w2v.w;
            p[12] += gv * w3v.x; p[13] += gv * w3v.y;
        }

        float z, ld;
        rqs_eval(p, xr[dim], z, ld);
        out[(size_t)dim * NR + row] = z;

#pragma unroll
        for (int o = 16; o > 0; o >>= 1) ld += __shfl_down_sync(0xffffffffu, ld, o);
        if ((tid & 31) == 0) redbuf[tid >> 5] = ld;
        __syncthreads();
        if (tid < 2)
            out2[dim * (NR/64) + rowblk * 2 + tid] = redbuf[2*tid] + redbuf[2*tid + 1];
        __syncthreads();   // redbuf + w*s reuse ordering
    }
}

extern "C" void kernel_launch(void* const* d_in, const int* in_sizes, int n_in,
                              void* d_out, int out_size)
{
    const float* x     = (const float*)d_in[0];
    const float* initp = (const float*)d_in[1];
    const float* W1    = (const float*)d_in[2];
    const float* b1    = (const float*)d_in[3];
    const float* W2    = (const float*)d_in[4];
    const float* b2    = (const float*)d_in[5];
    const float* W3    = (const float*)d_in[6];
    const float* b3    = (const float*)d_in[7];
    float* out = (float*)d_out;

    nsf_ar_kernel<<<NRB * NCH, TPB>>>(x, initp, W1, b1, W2, b2, W3, b3, out);
}

// round 9
// speedup vs baseline: 1.9527x; 1.1127x over previous
#include <cuda_runtime.h>

#define TPB   128
#define NR    32768
#define DD    64
#define LL    63
#define HH    8
#define PP    14
#define KB    5
#define NCH   8            // dim chunks; chunk c owns dims ≡ c (mod 8)
#define NRB   (NR / TPB)   // 256 row-blocks
#define BBf   5.0f
#define MINW  0.001f
#define MINH  0.001f
#define MIND  0.001f
#define XST   65   // padded smem stride -> conflict-free column reads

typedef unsigned long long u64;

__device__ __forceinline__ u64 ffma2(u64 a, u64 b, u64 c){
    u64 d; asm("fma.rn.f32x2 %0, %1, %2, %3;" : "=l"(d) : "l"(a), "l"(b), "l"(c)); return d;
}
__device__ __forceinline__ u64 pack2(float lo, float hi){
    u64 d; asm("mov.b64 %0, {%1, %2};" : "=l"(d) : "f"(lo), "f"(hi)); return d;
}
__device__ __forceinline__ void unpack2(u64 v, float& lo, float& hi){
    asm("mov.b64 {%0, %1}, %2;" : "=f"(lo), "=f"(hi) : "l"(v));
}
__device__ __forceinline__ float tanh_fast(float x){
    float y; asm("tanh.approx.f32 %0, %1;" : "=f"(y) : "f"(x)); return y;
}

__device__ __forceinline__ void rqs_eval(const float* p, float xf, float& z, float& ldout)
{
    bool inside = (xf >= -BBf) && (xf <= BBf);
    float xc = fminf(fmaxf(xf, -BBf), BBf);

    float ew[KB], eh[KB];
    float sw = 0.f, sh = 0.f;
#pragma unroll
    for (int k = 0; k < KB; k++){ ew[k] = __expf(p[k]);      sw += ew[k]; }
#pragma unroll
    for (int k = 0; k < KB; k++){ eh[k] = __expf(p[KB + k]); sh += eh[k]; }
    float aW = __fdividef(1.0f - KB * MINW, sw);
    float aH = __fdividef(1.0f - KB * MINH, sh);

    float curw = -BBf, curh = -BBf;
    float icw = -BBf, ich = -BBf, ibw = 1.f, ih = 1.f;
    float duL = 0.f, duR = 0.f;
    bool firstbin = true, lastbin = false;
#pragma unroll
    for (int k = 0; k < KB; k++){
        float nw = (k == KB-1) ? BBf : curw + 2.0f * BBf * (MINW + aW * ew[k]);
        float nh = (k == KB-1) ? BBf : curh + 2.0f * BBf * (MINH + aH * eh[k]);
        bool c = (k == 0) || (xc >= curw);
        if (c){
            icw = curw; ich = curh; ibw = nw - curw; ih = nh - curh;
            firstbin = (k == 0); lastbin = (k == KB-1);
            duL = (k == 0)      ? 0.f : p[2*KB + k - 1];
            duR = (k == KB-1)   ? 0.f : p[2*KB + k];
        }
        curw = nw; curh = nh;
    }
    float idv   = firstbin ? 1.0f : (MIND + __logf(1.0f + __expf(duL)));
    float idvp1 = lastbin  ? 1.0f : (MIND + __logf(1.0f + __expf(duR)));

    float rbw   = __fdividef(1.0f, ibw);
    float theta = (xc - icw) * rbw;
    float idl   = ih * rbw;
    float tmt   = theta * (1.0f - theta);
    float th2   = theta * theta;
    float num   = ih * (idl * th2 + idv * tmt);
    float den   = idl + (idv + idvp1 - 2.0f * idl) * tmt;
    float outv  = ich + __fdividef(num, den);
    float omt   = 1.0f - theta;
    float dnum  = idl * idl * (idvp1 * th2 + 2.0f * idl * tmt + idv * omt * omt);
    float lv    = __logf(dnum) - 2.0f * __logf(den);

    z     = inside ? outv : xf;
    ldout = inside ? lv   : 0.0f;
}

__global__ __launch_bounds__(TPB, 5)
void nsf_ar_kernel(const float* __restrict__ x,
                   const float* __restrict__ initp,
                   const float* __restrict__ W1,
                   const float* __restrict__ b1,
                   const float* __restrict__ W2,
                   const float* __restrict__ b2,
                   const float* __restrict__ W3,
                   const float* __restrict__ b3,
                   float* __restrict__ out)
{
    __shared__ __align__(16) float xsh[TPB * XST];
    __shared__ __align__(16) u64 w1p[LL * HH];     // (w_da, w_db) pairs
    __shared__ __align__(16) u64 w2p[HH * HH];
    __shared__ __align__(16) u64 w3p[HH * 16];     // padded to 16 cols
    __shared__ __align__(16) u64 b1p[HH], b2p[HH], b3p[16];
    __shared__ float redbuf[8];

    const int tid    = threadIdx.x;
    const int bid    = blockIdx.x;          // 0..2047
    const int rowblk = bid & (NRB - 1);     // 0..255
    const int chunk  = bid >> 8;            // 0..7
    const int row0   = rowblk * TPB;
    const int row    = row0 + tid;

    // stage x tile (coalesced global read, padded smem write)
    for (int i = tid; i < TPB * DD; i += TPB){
        int r = i / DD, c = i % DD;
        xsh[r * XST + c] = x[(row0 + r) * DD + c];
    }

    const float* xr = &xsh[tid * XST];
    float* out2 = out + (size_t)NR * DD;

    for (int k4 = 0; k4 < 4; k4++){
        const int da = chunk + 16 * k4;     // lo dim (da==0 only for chunk 0, k4 0)
        const int db = da + 8;              // hi dim
        const int la = da - 1;              // may be -1
        const int lb = db - 1;

        // ---- stage paired weights (lo lane: W1 rows beyond la are zero by input masking) ----
        __syncthreads();   // protect smem reuse from previous iteration
        {
            const int n1 = (lb + 1) * HH;
            const float* W1a = W1 + (size_t)la * (LL*HH);
            const float* W1b = W1 + (size_t)lb * (LL*HH);
            for (int e = tid; e < n1; e += TPB){
                float lo = (la >= 0) ? W1a[e] : 0.f;
                w1p[e] = pack2(lo, W1b[e]);
            }
            if (tid < HH * HH){
                float lo = (la >= 0) ? W2[la * (HH*HH) + tid] : 0.f;
                w2p[tid] = pack2(lo, W2[lb * (HH*HH) + tid]);
            }
            for (int e = tid; e < HH * PP; e += TPB){
                int g = e / PP, c = e % PP;
                float lo = (la >= 0) ? W3[la * (HH*PP) + e] : 0.f;
                w3p[g * 16 + c] = pack2(lo, W3[lb * (HH*PP) + e]);
            }
            if (tid >= 112 && tid < 128){   // zero pad cols 14,15
                int u = tid - 112;
                w3p[(u >> 1) * 16 + 14 + (u & 1)] = 0ULL;
            }
            if (tid < HH){
                float lo = (la >= 0) ? b1[la * HH + tid] : 0.f;
                b1p[tid] = pack2(lo, b1[lb * HH + tid]);
            } else if (tid < 2*HH){
                int h = tid - HH;
                float lo = (la >= 0) ? b2[la * HH + h] : 0.f;
                b2p[h] = pack2(lo, b2[lb * HH + h]);
            } else if (tid < 2*HH + PP){
                int c = tid - 2*HH;
                float lo = (la >= 0) ? b3[la * PP + c] : 0.f;
                b3p[c] = pack2(lo, b3[lb * PP + c]);
            } else if (tid < 2*HH + 16){
                b3p[tid - 2*HH] = 0ULL;
            }
        }
        __syncthreads();

        // ---- layer 1 (paired): a1p[h] += (x, x) * (w_da, w_db) ----
        u64 a1p[HH];
#pragma unroll
        for (int h = 0; h < HH; h++) a1p[h] = b1p[h];
#pragma unroll 4
        for (int j = 0; j <= lb; j++){
            float xv = xr[j];
            u64 xp = pack2(xv, xv);
            const ulonglong2* wp = reinterpret_cast<const ulonglong2*>(&w1p[j * 8]);
            ulonglong2 q0 = wp[0], q1 = wp[1], q2 = wp[2], q3 = wp[3];
            a1p[0] = ffma2(xp, q0.x, a1p[0]); a1p[1] = ffma2(xp, q0.y, a1p[1]);
            a1p[2] = ffma2(xp, q1.x, a1p[2]); a1p[3] = ffma2(xp, q1.y, a1p[3]);
            a1p[4] = ffma2(xp, q2.x, a1p[4]); a1p[5] = ffma2(xp, q2.y, a1p[5]);
            a1p[6] = ffma2(xp, q3.x, a1p[6]); a1p[7] = ffma2(xp, q3.y, a1p[7]);
        }
#pragma unroll
        for (int h = 0; h < HH; h++){
            float lo, hi; unpack2(a1p[h], lo, hi);
            a1p[h] = pack2(tanh_fast(lo), tanh_fast(hi));
        }

        // ---- layer 2 (paired) ----
        u64 a2p[HH];
#pragma unroll
        for (int g = 0; g < HH; g++) a2p[g] = b2p[g];
#pragma unroll
        for (int h = 0; h < HH; h++){
            u64 hv = a1p[h];
            const ulonglong2* wp = reinterpret_cast<const ulonglong2*>(&w2p[h * 8]);
            ulonglong2 q0 = wp[0], q1 = wp[1], q2 = wp[2], q3 = wp[3];
            a2p[0] = ffma2(hv, q0.x, a2p[0]); a2p[1] = ffma2(hv, q0.y, a2p[1]);
            a2p[2] = ffma2(hv, q1.x, a2p[2]); a2p[3] = ffma2(hv, q1.y, a2p[3]);
            a2p[4] = ffma2(hv, q2.x, a2p[4]); a2p[5] = ffma2(hv, q2.y, a2p[5]);
            a2p[6] = ffma2(hv, q3.x, a2p[6]); a2p[7] = ffma2(hv, q3.y, a2p[7]);
        }
#pragma unroll
        for (int g = 0; g < HH; g++){
            float lo, hi; unpack2(a2p[g], lo, hi);
            a2p[g] = pack2(tanh_fast(lo), tanh_fast(hi));
        }

        // ---- layer 3 (paired, 16 padded outputs) ----
        u64 pu[16];
#pragma unroll
        for (int c = 0; c < 16; c++) pu[c] = b3p[c];
#pragma unroll
        for (int g = 0; g < HH; g++){
            u64 gv = a2p[g];
            const ulonglong2* wp = reinterpret_cast<const ulonglong2*>(&w3p[g * 16]);
            ulonglong2 q0 = wp[0], q1 = wp[1], q2 = wp[2], q3 = wp[3];
            ulonglong2 q4 = wp[4], q5 = wp[5], q6 = wp[6], q7 = wp[7];
            pu[0]  = ffma2(gv, q0.x, pu[0]);  pu[1]  = ffma2(gv, q0.y, pu[1]);
            pu[2]  = ffma2(gv, q1.x, pu[2]);  pu[3]  = ffma2(gv, q1.y, pu[3]);
            pu[4]  = ffma2(gv, q2.x, pu[4]);  pu[5]  = ffma2(gv, q2.y, pu[5]);
            pu[6]  = ffma2(gv, q3.x, pu[6]);  pu[7]  = ffma2(gv, q3.y, pu[7]);
            pu[8]  = ffma2(gv, q4.x, pu[8]);  pu[9]  = ffma2(gv, q4.y, pu[9]);
            pu[10] = ffma2(gv, q5.x, pu[10]); pu[11] = ffma2(gv, q5.y, pu[11]);
            pu[12] = ffma2(gv, q6.x, pu[12]); pu[13] = ffma2(gv, q6.y, pu[13]);
        }

        // ---- unpack params, run both splines (scalar, 2-way ILP) ----
        float pa[PP], pb[PP];
#pragma unroll
        for (int c = 0; c < PP; c++) unpack2(pu[c], pa[c], pb[c]);
        if (da == 0){
#pragma unroll
            for (int c = 0; c < PP; c++) pa[c] = initp[c];
        }

        float za, lda, zb, ldb;
        rqs_eval(pa, xr[da], za, lda);
        rqs_eval(pb, xr[db], zb, ldb);
        out[(size_t)da * NR + row] = za;
        out[(size_t)db * NR + row] = zb;

#pragma unroll
        for (int o = 16; o > 0; o >>= 1){
            lda += __shfl_down_sync(0xffffffffu, lda, o);
            ldb += __shfl_down_sync(0xffffffffu, ldb, o);
        }
        if ((tid & 31) == 0){
            redbuf[tid >> 5]     = lda;
            redbuf[4 + (tid >> 5)] = ldb;
        }
        __syncthreads();
        if (tid < 2)
            out2[da * (NR/64) + rowblk * 2 + tid] = redbuf[2*tid] + redbuf[2*tid + 1];
        else if (tid < 4){
            int t = tid - 2;
            out2[db * (NR/64) + rowblk * 2 + t] = redbuf[4 + 2*t] + redbuf[4 + 2*t + 1];
        }
        // leading __syncthreads of next iteration protects redbuf/w*p reuse
    }
}

extern "C" void kernel_launch(void* const* d_in, const int* in_sizes, int n_in,
                              void* d_out, int out_size)
{
    const float* x     = (const float*)d_in[0];
    const float* initp = (const float*)d_in[1];
    const float* W1    = (const float*)d_in[2];
    const float* b1    = (const float*)d_in[3];
    const float* W2    = (const float*)d_in[4];
    const float* b2    = (const float*)d_in[5];
    const float* W3    = (const float*)d_in[6];
    const float* b3    = (const float*)d_in[7];
    float* out = (float*)d_out;

    nsf_ar_kernel<<<NRB * NCH, TPB>>>(x, initp, W1, b1, W2, b2, W3, b3, out);
}

// round 12
// speedup vs baseline: 2.0829x; 1.0667x over previous
#include <cuda_runtime.h>

#define TPB   128
#define NR    32768
#define DD    64
#define LL    63
#define HH    8
#define PP    14
#define KB    5
#define NCH   8            // dim chunks; chunk c owns dims ≡ c (mod 8)
#define NRB   (NR / TPB)   // 256 row-blocks
#define BBf   5.0f
#define MINW  0.001f
#define MINH  0.001f
#define MIND  0.001f
#define XST   65   // padded smem stride -> conflict-free column reads

typedef unsigned long long u64;

__device__ __forceinline__ u64 ffma2(u64 a, u64 b, u64 c){
    u64 d; asm("fma.rn.f32x2 %0, %1, %2, %3;" : "=l"(d) : "l"(a), "l"(b), "l"(c)); return d;
}
__device__ __forceinline__ u64 pack2(float lo, float hi){
    u64 d; asm("mov.b64 %0, {%1, %2};" : "=l"(d) : "f"(lo), "f"(hi)); return d;
}
__device__ __forceinline__ void unpack2(u64 v, float& lo, float& hi){
    asm("mov.b64 {%0, %1}, %2;" : "=f"(lo), "=f"(hi) : "l"(v));
}
__device__ __forceinline__ float tanh_fast(float x){
    float y; asm("tanh.approx.f32 %0, %1;" : "=f"(y) : "f"(x)); return y;
}

// Two independent RQS evaluations, manually interleaved for 2-way ILP through
// the MUFU (exp/log/rcp) dependency chains.
__device__ __forceinline__ void rqs_eval2(const float* pa, float xa,
                                          const float* pb, float xb,
                                          float& za, float& lda,
                                          float& zb, float& ldb)
{
    bool ina = (xa >= -BBf) && (xa <= BBf);
    bool inb = (xb >= -BBf) && (xb <= BBf);
    float xca = fminf(fmaxf(xa, -BBf), BBf);
    float xcb = fminf(fmaxf(xb, -BBf), BBf);

    float ewa[KB], eha[KB], ewb[KB], ehb[KB];
    float swa = 0.f, sha = 0.f, swb = 0.f, shb = 0.f;
#pragma unroll
    for (int k = 0; k < KB; k++){
        ewa[k] = __expf(pa[k]);      ewb[k] = __expf(pb[k]);
        swa += ewa[k];               swb += ewb[k];
    }
#pragma unroll
    for (int k = 0; k < KB; k++){
        eha[k] = __expf(pa[KB + k]); ehb[k] = __expf(pb[KB + k]);
        sha += eha[k];               shb += ehb[k];
    }
    float aWa = __fdividef(1.0f - KB * MINW, swa);
    float aWb = __fdividef(1.0f - KB * MINW, swb);
    float aHa = __fdividef(1.0f - KB * MINH, sha);
    float aHb = __fdividef(1.0f - KB * MINH, shb);

    float cwa = -BBf, cha = -BBf, cwb = -BBf, chb = -BBf;
    float icwa = -BBf, icha = -BBf, ibwa = 1.f, iha = 1.f;
    float icwb = -BBf, ichb = -BBf, ibwb = 1.f, ihb = 1.f;
    float duLa = 0.f, duRa = 0.f, duLb = 0.f, duRb = 0.f;
    bool fba = true, lba = false, fbb = true, lbb = false;
#pragma unroll
    for (int k = 0; k < KB; k++){
        float nwa = (k == KB-1) ? BBf : cwa + 2.0f * BBf * (MINW + aWa * ewa[k]);
        float nwb = (k == KB-1) ? BBf : cwb + 2.0f * BBf * (MINW + aWb * ewb[k]);
        float nha = (k == KB-1) ? BBf : cha + 2.0f * BBf * (MINH + aHa * eha[k]);
        float nhb = (k == KB-1) ? BBf : chb + 2.0f * BBf * (MINH + aHb * ehb[k]);
        bool ca = (k == 0) || (xca >= cwa);
        bool cb = (k == 0) || (xcb >= cwb);
        if (ca){
            icwa = cwa; icha = cha; ibwa = nwa - cwa; iha = nha - cha;
            fba = (k == 0); lba = (k == KB-1);
            duLa = (k == 0)    ? 0.f : pa[2*KB + k - 1];
            duRa = (k == KB-1) ? 0.f : pa[2*KB + k];
        }
        if (cb){
            icwb = cwb; ichb = chb; ibwb = nwb - cwb; ihb = nhb - chb;
            fbb = (k == 0); lbb = (k == KB-1);
            duLb = (k == 0)    ? 0.f : pb[2*KB + k - 1];
            duRb = (k == KB-1) ? 0.f : pb[2*KB + k];
        }
        cwa = nwa; cha = nha; cwb = nwb; chb = nhb;
    }
    float idva  = fba ? 1.0f : (MIND + __logf(1.0f + __expf(duLa)));
    float idvb  = fbb ? 1.0f : (MIND + __logf(1.0f + __expf(duLb)));
    float idp1a = lba ? 1.0f : (MIND + __logf(1.0f + __expf(duRa)));
    float idp1b = lbb ? 1.0f : (MIND + __logf(1.0f + __expf(duRb)));

    float rba = __fdividef(1.0f, ibwa);
    float rbb = __fdividef(1.0f, ibwb);
    float tha = (xca - icwa) * rba;
    float thb = (xcb - icwb) * rbb;
    float idla = iha * rba;
    float idlb = ihb * rbb;
    float tma = tha * (1.0f - tha);
    float tmb = thb * (1.0f - thb);
    float t2a = tha * tha;
    float t2b = thb * thb;
    float numa = iha * (idla * t2a + idva * tma);
    float numb = ihb * (idlb * t2b + idvb * tmb);
    float dena = idla + (idva + idp1a - 2.0f * idla) * tma;
    float denb = idlb + (idvb + idp1b - 2.0f * idlb) * tmb;
    float outa = icha + __fdividef(numa, dena);
    float outb = ichb + __fdividef(numb, denb);
    float oma = 1.0f - tha;
    float omb = 1.0f - thb;
    float dna = idla * idla * (idp1a * t2a + 2.0f * idla * tma + idva * oma * oma);
    float dnb = idlb * idlb * (idp1b * t2b + 2.0f * idlb * tmb + idvb * omb * omb);
    float lva = __logf(dna) - 2.0f * __logf(dena);
    float lvb = __logf(dnb) - 2.0f * __logf(denb);

    za  = ina ? outa : xa;
    zb  = inb ? outb : xb;
    lda = ina ? lva  : 0.0f;
    ldb = inb ? lvb  : 0.0f;
}

__global__ __launch_bounds__(TPB, 5)
void nsf_ar_kernel(const float* __restrict__ x,
                   const float* __restrict__ initp,
                   const float* __restrict__ W1,
                   const float* __restrict__ b1,
                   const float* __restrict__ W2,
                   const float* __restrict__ b2,
                   const float* __restrict__ W3,
                   const float* __restrict__ b3,
                   float* __restrict__ out)
{
    __shared__ __align__(16) float xsh[TPB * XST];
    __shared__ __align__(16) u64 w1p[2][LL * HH];
    __shared__ __align__(16) u64 w2p[2][HH * HH];
    __shared__ __align__(16) u64 w3p[2][HH * 16];
    __shared__ __align__(16) u64 b1p[2][HH], b2p[2][HH], b3p[2][16];
    __shared__ float redbuf[8];

    const int tid    = threadIdx.x;
    const int bid    = blockIdx.x;          // 0..2047
    const int rowblk = bid & (NRB - 1);     // 0..255
    const int chunk  = bid >> 8;            // 0..7
    const int row0   = rowblk * TPB;
    const int row    = row0 + tid;

    // stage x tile (coalesced global read, padded smem write)
    for (int i = tid; i < TPB * DD; i += TPB){
        int r = i / DD, c = i % DD;
        xsh[r * XST + c] = x[(row0 + r) * DD + c];
    }

    const float* xr = &xsh[tid * XST];
    float* out2 = out + (size_t)NR * DD;

    // ---- staging lambda: pair k4 -> buffer bb ----
    auto stage = [&](int k4, int bb){
        const int da = chunk + 16 * k4;
        const int la = da - 1;              // may be -1
        const int lb = da + 7;              // db - 1
        const int n1 = (lb + 1) * HH;
        const float* W1a = W1 + (size_t)la * (LL*HH);
        const float* W1b = W1 + (size_t)lb * (LL*HH);
        for (int e = tid; e < n1; e += TPB){
            float lo = (la >= 0) ? W1a[e] : 0.f;
            w1p[bb][e] = pack2(lo, W1b[e]);
        }
        if (tid < HH * HH){
            float lo = (la >= 0) ? W2[la * (HH*HH) + tid] : 0.f;
            w2p[bb][tid] = pack2(lo, W2[lb * (HH*HH) + tid]);
        }
        for (int e = tid; e < HH * PP; e += TPB){
            int g = e / PP, c = e % PP;
            float lo = (la >= 0) ? W3[la * (HH*PP) + e] : 0.f;
            w3p[bb][g * 16 + c] = pack2(lo, W3[lb * (HH*PP) + e]);
        }
        if (tid >= 112 && tid < 128){       // zero pad cols 14,15
            int u = tid - 112;
            w3p[bb][(u >> 1) * 16 + 14 + (u & 1)] = 0ULL;
        }
        if (tid < HH){
            float lo = (la >= 0) ? b1[la * HH + tid] : 0.f;
            b1p[bb][tid] = pack2(lo, b1[lb * HH + tid]);
        } else if (tid < 2*HH){
            int h = tid - HH;
            float lo = (la >= 0) ? b2[la * HH + h] : 0.f;
            b2p[bb][h] = pack2(lo, b2[lb * HH + h]);
        } else if (tid < 2*HH + PP){
            int c = tid - 2*HH;
            float lo = (la >= 0) ? b3[la * PP + c] : 0.f;
            b3p[bb][c] = pack2(lo, b3[lb * PP + c]);
        } else if (tid < 2*HH + 16){
            b3p[bb][tid - 2*HH] = 0ULL;
        }
    };

    stage(0, 0);
    __syncthreads();   // also covers xsh staging

#pragma unroll
    for (int k4 = 0; k4 < 4; k4++){
        const int bb = k4 & 1;
        const int da = chunk + 16 * k4;
        const int db = da + 8;
        const int lb = db - 1;

        // kick off next pair's staging into the other buffer (overlaps compute)
        if (k4 < 3) stage(k4 + 1, bb ^ 1);

        // ---- layer 1 (paired dims): a1p[h] += (x, x) * (w_da, w_db) ----
        u64 a1p[HH];
#pragma unroll
        for (int h = 0; h < HH; h++) a1p[h] = b1p[bb][h];
#pragma unroll 4
        for (int j = 0; j <= lb; j++){
            float xv = xr[j];
            u64 xp = pack2(xv, xv);
            const ulonglong2* wp = reinterpret_cast<const ulonglong2*>(&w1p[bb][j * 8]);
            ulonglong2 q0 = wp[0], q1 = wp[1], q2 = wp[2], q3 = wp[3];
            a1p[0] = ffma2(xp, q0.x, a1p[0]); a1p[1] = ffma2(xp, q0.y, a1p[1]);
            a1p[2] = ffma2(xp, q1.x, a1p[2]); a1p[3] = ffma2(xp, q1.y, a1p[3]);
            a1p[4] = ffma2(xp, q2.x, a1p[4]); a1p[5] = ffma2(xp, q2.y, a1p[5]);
            a1p[6] = ffma2(xp, q3.x, a1p[6]); a1p[7] = ffma2(xp, q3.y, a1p[7]);
        }
#pragma unroll
        for (int h = 0; h < HH; h++){
            float lo, hi; unpack2(a1p[h], lo, hi);
            a1p[h] = pack2(tanh_fast(lo), tanh_fast(hi));
        }

        // ---- layer 2 (paired) ----
        u64 a2p[HH];
#pragma unroll
        for (int g = 0; g < HH; g++) a2p[g] = b2p[bb][g];
#pragma unroll
        for (int h = 0; h < HH; h++){
            u64 hv = a1p[h];
            const ulonglong2* wp = reinterpret_cast<const ulonglong2*>(&w2p[bb][h * 8]);
            ulonglong2 q0 = wp[0], q1 = wp[1], q2 = wp[2], q3 = wp[3];
            a2p[0] = ffma2(hv, q0.x, a2p[0]); a2p[1] = ffma2(hv, q0.y, a2p[1]);
            a2p[2] = ffma2(hv, q1.x, a2p[2]); a2p[3] = ffma2(hv, q1.y, a2p[3]);
            a2p[4] = ffma2(hv, q2.x, a2p[4]); a2p[5] = ffma2(hv, q2.y, a2p[5]);
            a2p[6] = ffma2(hv, q3.x, a2p[6]); a2p[7] = ffma2(hv, q3.y, a2p[7]);
        }
#pragma unroll
        for (int g = 0; g < HH; g++){
            float lo, hi; unpack2(a2p[g], lo, hi);
            a2p[g] = pack2(tanh_fast(lo), tanh_fast(hi));
        }

        // ---- layer 3 (paired, 16 padded outputs) ----
        u64 pu[16];
#pragma unroll
        for (int c = 0; c < 16; c++) pu[c] = b3p[bb][c];
#pragma unroll
        for (int g = 0; g < HH; g++){
            u64 gv = a2p[g];
            const ulonglong2* wp = reinterpret_cast<const ulonglong2*>(&w3p[bb][g * 16]);
            ulonglong2 q0 = wp[0], q1 = wp[1], q2 = wp[2], q3 = wp[3];
            ulonglong2 q4 = wp[4], q5 = wp[5], q6 = wp[6];
            pu[0]  = ffma2(gv, q0.x, pu[0]);  pu[1]  = ffma2(gv, q0.y, pu[1]);
            pu[2]  = ffma2(gv, q1.x, pu[2]);  pu[3]  = ffma2(gv, q1.y, pu[3]);
            pu[4]  = ffma2(gv, q2.x, pu[4]);  pu[5]  = ffma2(gv, q2.y, pu[5]);
            pu[6]  = ffma2(gv, q3.x, pu[6]);  pu[7]  = ffma2(gv, q3.y, pu[7]);
            pu[8]  = ffma2(gv, q4.x, pu[8]);  pu[9]  = ffma2(gv, q4.y, pu[9]);
            pu[10] = ffma2(gv, q5.x, pu[10]); pu[11] = ffma2(gv, q5.y, pu[11]);
            pu[12] = ffma2(gv, q6.x, pu[12]); pu[13] = ffma2(gv, q6.y, pu[13]);
        }

        // ---- unpack params, run both splines (interleaved) ----
        float pa[PP], pb[PP];
#pragma unroll
        for (int c = 0; c < PP; c++) unpack2(pu[c], pa[c], pb[c]);
        if (da == 0){
#pragma unroll
            for (int c = 0; c < PP; c++) pa[c] = initp[c];
        }

        float za, lda, zb, ldb;
        rqs_eval2(pa, xr[da], pb, xr[db], za, lda, zb, ldb);
        out[(size_t)da * NR + row] = za;
        out[(size_t)db * NR + row] = zb;

#pragma unroll
        for (int o = 16; o > 0; o >>= 1){
            lda += __shfl_down_sync(0xffffffffu, lda, o);
            ldb += __shfl_down_sync(0xffffffffu, ldb, o);
        }
        if ((tid & 31) == 0){
            redbuf[tid >> 5]       = lda;
            redbuf[4 + (tid >> 5)] = ldb;
        }
        __syncthreads();   // orders redbuf AND protects buf[bb] for next-next staging
        if (tid < 2)
            out2[da * (NR/64) + rowblk * 2 + tid] = redbuf[2*tid] + redbuf[2*tid + 1];
        else if (tid < 4){
            int t = tid - 2;
            out2[db * (NR/64) + rowblk * 2 + t] = redbuf[4 + 2*t] + redbuf[4 + 2*t + 1];
        }
        if (k4 < 3) __syncthreads();   // redbuf read-before-overwrite for next iter
    }
}

extern "C" void kernel_launch(void* const* d_in, const int* in_sizes, int n_in,
                              void* d_out, int out_size)
{
    const float* x     = (const float*)d_in[0];
    const float* initp = (const float*)d_in[1];
    const float* W1    = (const float*)d_in[2];
    const float* b1    = (const float*)d_in[3];
    const float* W2    = (const float*)d_in[4];
    const float* b2    = (const float*)d_in[5];
    const float* W3    = (const float*)d_in[6];
    const float* b3    = (const float*)d_in[7];
    float* out = (float*)d_out;

    nsf_ar_kernel<<<NRB * NCH, TPB>>>(x, initp, W1, b1, W2, b2, W3, b3, out);
}

// round 13
// speedup vs baseline: 2.1443x; 1.0295x over previous
#include <cuda_runtime.h>

#define TPB   128
#define NR    32768
#define DD    64
#define HH    8
#define PP    14
#define KB    5
#define NCH   8            // dim chunks; chunk c owns dims ≡ c (mod 8)
#define NRB   (NR / TPB)   // 256 row-blocks
#define BBf   5.0f
#define MINW  0.001f
#define MINH  0.001f
#define MIND  0.001f
#define XST   65           // padded smem stride -> conflict-free column reads
#define BLOB  728          // u64 per (chunk,k4) weight blob: w2[64] w3[128] b1[8] b2[8] b3[16] w1[<=504]
#define OFF_W2 0
#define OFF_W3 64
#define OFF_B1 192
#define OFF_B2 200
#define OFF_B3 208
#define OFF_W1 224

typedef unsigned long long u64;

// prepacked weights: 32 blobs of 728 u64 (pidx = k4*8 + chunk)
__device__ __align__(16) u64 g_pack[32 * BLOB];

__device__ __forceinline__ u64 ffma2(u64 a, u64 b, u64 c){
    u64 d; asm("fma.rn.f32x2 %0, %1, %2, %3;" : "=l"(d) : "l"(a), "l"(b), "l"(c)); return d;
}
__device__ __forceinline__ u64 pack2(float lo, float hi){
    u64 d; asm("mov.b64 %0, {%1, %2};" : "=l"(d) : "f"(lo), "f"(hi)); return d;
}
__device__ __forceinline__ void unpack2(u64 v, float& lo, float& hi){
    asm("mov.b64 {%0, %1}, %2;" : "=f"(lo), "=f"(hi) : "l"(v));
}
__device__ __forceinline__ float tanh_fast(float x){
    float y; asm("tanh.approx.f32 %0, %1;" : "=f"(y) : "f"(x)); return y;
}
__device__ __forceinline__ unsigned smem_u32(const void* p){
    return (unsigned)__cvta_generic_to_shared(p);
}
__device__ __forceinline__ void mbar_init(unsigned a, unsigned cnt){
    asm volatile("mbarrier.init.shared.b64 [%0], %1;" :: "r"(a), "r"(cnt) : "memory");
}
__device__ __forceinline__ void mbar_expect_tx(unsigned a, unsigned bytes){
    asm volatile("mbarrier.arrive.expect_tx.shared.b64 _, [%0], %1;" :: "r"(a), "r"(bytes) : "memory");
}
__device__ __forceinline__ void mbar_arrive(unsigned a){
    asm volatile("mbarrier.arrive.shared.b64 _, [%0];" :: "r"(a) : "memory");
}
__device__ __forceinline__ void mbar_wait(unsigned a, unsigned phase){
    asm volatile(
        "{\n\t.reg .pred P;\n\t"
        "WAITLP_%=:\n\t"
        "mbarrier.try_wait.parity.acquire.cta.shared::cta.b64 P, [%0], %1, 0x989680;\n\t"
        "@P bra.uni WAITDN_%=;\n\t"
        "bra.uni WAITLP_%=;\n\t"
        "WAITDN_%=:\n\t}"
        :: "r"(a), "r"(phase) : "memory");
}
__device__ __forceinline__ void bulk_g2s(unsigned dst, const void* src, unsigned bytes, unsigned mbar){
    asm volatile(
        "cp.async.bulk.shared::cta.global.mbarrier::complete_tx::bytes [%0], [%1], %2, [%3];"
        :: "r"(dst), "l"(src), "r"(bytes), "r"(mbar) : "memory");
}

// ---------------- prepack kernel: interleave (lo,hi) weight pairs ----------------
__global__ void prepack_kernel(const float* __restrict__ W1, const float* __restrict__ b1,
                               const float* __restrict__ W2, const float* __restrict__ b2,
                               const float* __restrict__ W3, const float* __restrict__ b3)
{
    const int pidx  = blockIdx.x;        // k4*8 + chunk
    const int k4    = pidx >> 3;
    const int chunk = pidx & 7;
    const int da = chunk + 16 * k4;
    const int la = da - 1;               // may be -1 (lo lane zeros)
    const int lb = da + 7;
    u64* dst = g_pack + (size_t)pidx * BLOB;
    const int tid = threadIdx.x;

    if (tid < 64){
        float lo = (la >= 0) ? W2[la * 64 + tid] : 0.f;
        dst[OFF_W2 + tid] = pack2(lo, W2[lb * 64 + tid]);
    }
    if (tid < 128){                      // w3: 8 rows x 16 padded cols
        int g = tid >> 4, c = tid & 15;
        u64 v = 0ULL;
        if (c < PP){
            float lo = (la >= 0) ? W3[la * (HH*PP) + g * PP + c] : 0.f;
            v = pack2(lo, W3[lb * (HH*PP) + g * PP + c]);
        }
        dst[OFF_W3 + tid] = v;
    }
    if (tid < HH){
        float l1v = (la >= 0) ? b1[la * HH + tid] : 0.f;
        dst[OFF_B1 + tid] = pack2(l1v, b1[lb * HH + tid]);
        float l2v = (la >= 0) ? b2[la * HH + tid] : 0.f;
        dst[OFF_B2 + tid] = pack2(l2v, b2[lb * HH + tid]);
    }
    if (tid < 16){
        u64 v = 0ULL;
        if (tid < PP){
            float lo = (la >= 0) ? b3[la * PP + tid] : 0.f;
            v = pack2(lo, b3[lb * PP + tid]);
        }
        dst[OFF_B3 + tid] = v;
    }
    const int n1 = (lb + 1) * HH;
    const float* W1a = W1 + (size_t)la * (63*HH);
    const float* W1b = W1 + (size_t)lb * (63*HH);
    for (int e = tid; e < n1; e += blockDim.x){
        float lo = (la >= 0) ? W1a[e] : 0.f;
        dst[OFF_W1 + e] = pack2(lo, W1b[e]);
    }
}

// Two independent RQS evaluations, interleaved for 2-way ILP through MUFU chains.
__device__ __forceinline__ void rqs_eval2(const float* pa, float xa,
                                          const float* pb, float xb,
                                          float& za, float& lda,
                                          float& zb, float& ldb)
{
    bool ina = (xa >= -BBf) && (xa <= BBf);
    bool inb = (xb >= -BBf) && (xb <= BBf);
    float xca = fminf(fmaxf(xa, -BBf), BBf);
    float xcb = fminf(fmaxf(xb, -BBf), BBf);

    float ewa[KB], eha[KB], ewb[KB], ehb[KB];
    float swa = 0.f, sha = 0.f, swb = 0.f, shb = 0.f;
#pragma unroll
    for (int k = 0; k < KB; k++){
        ewa[k] = __expf(pa[k]);      ewb[k] = __expf(pb[k]);
        swa += ewa[k];               swb += ewb[k];
    }
#pragma unroll
    for (int k = 0; k < KB; k++){
        eha[k] = __expf(pa[KB + k]); ehb[k] = __expf(pb[KB + k]);
        sha += eha[k];               shb += ehb[k];
    }
    float aWa = __fdividef(1.0f - KB * MINW, swa);
    float aWb = __fdividef(1.0f - KB * MINW, swb);
    float aHa = __fdividef(1.0f - KB * MINH, sha);
    float aHb = __fdividef(1.0f - KB * MINH, shb);

    float cwa = -BBf, cha = -BBf, cwb = -BBf, chb = -BBf;
    float icwa = -BBf, icha = -BBf, ibwa = 1.f, iha = 1.f;
    float icwb = -BBf, ichb = -BBf, ibwb = 1.f, ihb = 1.f;
    float duLa = 0.f, duRa = 0.f, duLb = 0.f, duRb = 0.f;
    bool fba = true, lba = false, fbb = true, lbb = false;
#pragma unroll
    for (int k = 0; k < KB; k++){
        float nwa = (k == KB-1) ? BBf : cwa + 2.0f * BBf * (MINW + aWa * ewa[k]);
        float nwb = (k == KB-1) ? BBf : cwb + 2.0f * BBf * (MINW + aWb * ewb[k]);
        float nha = (k == KB-1) ? BBf : cha + 2.0f * BBf * (MINH + aHa * eha[k]);
        float nhb = (k == KB-1) ? BBf : chb + 2.0f * BBf * (MINH + aHb * ehb[k]);
        bool ca = (k == 0) || (xca >= cwa);
        bool cb = (k == 0) || (xcb >= cwb);
        if (ca){
            icwa = cwa; icha = cha; ibwa = nwa - cwa; iha = nha - cha;
            fba = (k == 0); lba = (k == KB-1);
            duLa = (k == 0)    ? 0.f : pa[2*KB + k - 1];
            duRa = (k == KB-1) ? 0.f : pa[2*KB + k];
        }
        if (cb){
            icwb = cwb; ichb = chb; ibwb = nwb - cwb; ihb = nhb - chb;
            fbb = (k == 0); lbb = (k == KB-1);
            duLb = (k == 0)    ? 0.f : pb[2*KB + k - 1];
            duRb = (k == KB-1) ? 0.f : pb[2*KB + k];
        }
        cwa = nwa; cha = nha; cwb = nwb; chb = nhb;
    }
    float idva  = fba ? 1.0f : (MIND + __logf(1.0f + __expf(duLa)));
    float idvb  = fbb ? 1.0f : (MIND + __logf(1.0f + __expf(duLb)));
    float idp1a = lba ? 1.0f : (MIND + __logf(1.0f + __expf(duRa)));
    float idp1b = lbb ? 1.0f : (MIND + __logf(1.0f + __expf(duRb)));

    float rba = __fdividef(1.0f, ibwa);
    float rbb = __fdividef(1.0f, ibwb);
    float tha = (xca - icwa) * rba;
    float thb = (xcb - icwb) * rbb;
    float idla = iha * rba;
    float idlb = ihb * rbb;
    float tma = tha * (1.0f - tha);
    float tmb = thb * (1.0f - thb);
    float t2a = tha * tha;
    float t2b = thb * thb;
    float numa = iha * (idla * t2a + idva * tma);
    float numb = ihb * (idlb * t2b + idvb * tmb);
    float dena = idla + (idva + idp1a - 2.0f * idla) * tma;
    float denb = idlb + (idvb + idp1b - 2.0f * idlb) * tmb;
    float outa = icha + __fdividef(numa, dena);
    float outb = ichb + __fdividef(numb, denb);
    float oma = 1.0f - tha;
    float omb = 1.0f - thb;
    float dna = idla * idla * (idp1a * t2a + 2.0f * idla * tma + idva * oma * oma);
    float dnb = idlb * idlb * (idp1b * t2b + 2.0f * idlb * tmb + idvb * omb * omb);
    float lva = __logf(dna) - 2.0f * __logf(dena);
    float lvb = __logf(dnb) - 2.0f * __logf(denb);

    za  = ina ? outa : xa;
    zb  = inb ? outb : xb;
    lda = ina ? lva  : 0.0f;
    ldb = inb ? lvb  : 0.0f;
}

__global__ __launch_bounds__(TPB, 5)
void nsf_ar_kernel(const float* __restrict__ x,
                   const float* __restrict__ initp,
                   float* __restrict__ out)
{
    __shared__ __align__(16) float xsh[TPB * XST];
    __shared__ __align__(16) u64 wbuf[2][BLOB];
    __shared__ __align__(8)  u64 mbar_full[2], mbar_empty[2];
    __shared__ float redbuf[2][8];

    const int tid    = threadIdx.x;
    const int warp   = tid >> 5;
    const int bid    = blockIdx.x;          // 0..2047
    const int rowblk = bid & (NRB - 1);     // 0..255
    const int chunk  = bid >> 8;            // 0..7
    const int row0   = rowblk * TPB;
    const int row    = row0 + tid;

    const unsigned a_full[2]  = { smem_u32(&mbar_full[0]),  smem_u32(&mbar_full[1])  };
    const unsigned a_empty[2] = { smem_u32(&mbar_empty[0]), smem_u32(&mbar_empty[1]) };
    const unsigned a_wbuf[2]  = { smem_u32(&wbuf[0][0]),    smem_u32(&wbuf[1][0])    };

    if (tid == 0){
        mbar_init(a_full[0], 1);  mbar_init(a_full[1], 1);
        mbar_init(a_empty[0], 4); mbar_init(a_empty[1], 4);
    }

    // stage x tile (coalesced global read, padded smem write)
    for (int i = tid; i < TPB * DD; i += TPB){
        int r = i / DD, c = i % DD;
        xsh[r * XST + c] = x[(row0 + r) * DD + c];
    }
    __syncthreads();   // mbarrier init + xsh visible to all

    if (tid == 0){
        asm volatile("fence.proxy.async.shared::cta;" ::: "memory");
        unsigned sz0 = (unsigned)((OFF_W1 + (chunk + 8) * HH) * 8);
        mbar_expect_tx(a_full[0], sz0);
        bulk_g2s(a_wbuf[0], (const void*)(g_pack + (size_t)chunk * BLOB), sz0, a_full[0]);
    }

    const float* xr = &xsh[tid * XST];
    float* out2 = out + (size_t)NR * DD;

#pragma unroll
    for (int k4 = 0; k4 < 4; k4++){
        const int s  = k4 & 1;
        const int ph = (k4 >> 1) & 1;
        const int da = chunk + 16 * k4;
        const int db = da + 8;
        const int lb = db - 1;

        // producer: issue next pair's copy into the other buffer
        if (tid == 0 && k4 < 3){
            const int t = s ^ 1;
            if (k4 >= 1) mbar_wait(a_empty[t], 0);   // wait consumers done with buf t
            unsigned sz = (unsigned)((OFF_W1 + (chunk + 16 * (k4 + 1) + 8) * HH) * 8);
            mbar_expect_tx(a_full[t], sz);
            bulk_g2s(a_wbuf[t], (const void*)(g_pack + (size_t)((k4 + 1) * 8 + chunk) * BLOB),
                     sz, a_full[t]);
        }

        // consumer: wait this pair's weights
        mbar_wait(a_full[s], (unsigned)ph);
        const u64* wb = wbuf[s];

        // ---- layer 1 (paired dims): a1p[h] += (x, x) * (w_da, w_db) ----
        u64 a1p[HH];
#pragma unroll
        for (int h = 0; h < HH; h++) a1p[h] = wb[OFF_B1 + h];
#pragma unroll 4
        for (int j = 0; j <= lb; j++){
            float xv = xr[j];
            u64 xp = pack2(xv, xv);
            const ulonglong2* wp = reinterpret_cast<const ulonglong2*>(&wb[OFF_W1 + j * 8]);
            ulonglong2 q0 = wp[0], q1 = wp[1], q2 = wp[2], q3 = wp[3];
            a1p[0] = ffma2(xp, q0.x, a1p[0]); a1p[1] = ffma2(xp, q0.y, a1p[1]);
            a1p[2] = ffma2(xp, q1.x, a1p[2]); a1p[3] = ffma2(xp, q1.y, a1p[3]);
            a1p[4] = ffma2(xp, q2.x, a1p[4]); a1p[5] = ffma2(xp, q2.y, a1p[5]);
            a1p[6] = ffma2(xp, q3.x, a1p[6]); a1p[7] = ffma2(xp, q3.y, a1p[7]);
        }
#pragma unroll
        for (int h = 0; h < HH; h++){
            float lo, hi; unpack2(a1p[h], lo, hi);
            a1p[h] = pack2(tanh_fast(lo), tanh_fast(hi));
        }

        // ---- layer 2 (paired) ----
        u64 a2p[HH];
#pragma unroll
        for (int g = 0; g < HH; g++) a2p[g] = wb[OFF_B2 + g];
#pragma unroll
        for (int h = 0; h < HH; h++){
            u64 hv = a1p[h];
            const ulonglong2* wp = reinterpret_cast<const ulonglong2*>(&wb[OFF_W2 + h * 8]);
            ulonglong2 q0 = wp[0], q1 = wp[1], q2 = wp[2], q3 = wp[3];
            a2p[0] = ffma2(hv, q0.x, a2p[0]); a2p[1] = ffma2(hv, q0.y, a2p[1]);
            a2p[2] = ffma2(hv, q1.x, a2p[2]); a2p[3] = ffma2(hv, q1.y, a2p[3]);
            a2p[4] = ffma2(hv, q2.x, a2p[4]); a2p[5] = ffma2(hv, q2.y, a2p[5]);
            a2p[6] = ffma2(hv, q3.x, a2p[6]); a2p[7] = ffma2(hv, q3.y, a2p[7]);
        }
#pragma unroll
        for (int g = 0; g < HH; g++){
            float lo, hi; unpack2(a2p[g], lo, hi);
            a2p[g] = pack2(tanh_fast(lo), tanh_fast(hi));
        }

        // ---- layer 3 (paired, 16 padded outputs) ----
        u64 pu[16];
#pragma unroll
        for (int c = 0; c < 16; c++) pu[c] = wb[OFF_B3 + c];
#pragma unroll
        for (int g = 0; g < HH; g++){
            u64 gv = a2p[g];
            const ulonglong2* wp = reinterpret_cast<const ulonglong2*>(&wb[OFF_W3 + g * 16]);
            ulonglong2 q0 = wp[0], q1 = wp[1], q2 = wp[2], q3 = wp[3];
            ulonglong2 q4 = wp[4], q5 = wp[5], q6 = wp[6];
            pu[0]  = ffma2(gv, q0.x, pu[0]);  pu[1]  = ffma2(gv, q0.y, pu[1]);
            pu[2]  = ffma2(gv, q1.x, pu[2]);  pu[3]  = ffma2(gv, q1.y, pu[3]);
            pu[4]  = ffma2(gv, q2.x, pu[4]);  pu[5]  = ffma2(gv, q2.y, pu[5]);
            pu[6]  = ffma2(gv, q3.x, pu[6]);  pu[7]  = ffma2(gv, q3.y, pu[7]);
            pu[8]  = ffma2(gv, q4.x, pu[8]);  pu[9]  = ffma2(gv, q4.y, pu[9]);
            pu[10] = ffma2(gv, q5.x, pu[10]); pu[11] = ffma2(gv, q5.y, pu[11]);
            pu[12] = ffma2(gv, q6.x, pu[12]); pu[13] = ffma2(gv, q6.y, pu[13]);
        }

        // all wbuf[s] reads done -> release buffer to producer (one arrive per warp)
        if ((tid & 31) == 0) mbar_arrive(a_empty[s]);

        // ---- unpack params, run both splines (interleaved) ----
        float pa[PP], pb[PP];
#pragma unroll
        for (int c = 0; c < PP; c++) unpack2(pu[c], pa[c], pb[c]);
        if (da == 0){
#pragma unroll
            for (int c = 0; c < PP; c++) pa[c] = initp[c];
        }

        float za, lda, zb, ldb;
        rqs_eval2(pa, xr[da], pb, xr[db], za, lda, zb, ldb);
        out[(size_t)da * NR + row] = za;
        out[(size_t)db * NR + row] = zb;

        // ---- logdet partial sums: warp-pair reduction via named barriers ----
#pragma unroll
        for (int o = 16; o > 0; o >>= 1){
            lda += __shfl_down_sync(0xffffffffu, lda, o);
            ldb += __shfl_down_sync(0xffffffffu, ldb, o);
        }
        const int par = k4 & 1;
        if ((tid & 31) == 0){
            redbuf[par][warp]     = lda;
            redbuf[par][4 + warp] = ldb;
        }
        const int grp = warp >> 1;   // 0: warps 0,1  |  1: warps 2,3
        asm volatile("bar.sync %0, 64;" :: "r"(1 + grp) : "memory");
        if ((tid & 63) == 0){
            out2[da * (NR/64) + rowblk * 2 + grp] =
                redbuf[par][2*grp]     + redbuf[par][2*grp + 1];
            out2[db * (NR/64) + rowblk * 2 + grp] =
                redbuf[par][4 + 2*grp] + redbuf[par][4 + 2*grp + 1];
        }
        // redbuf reuse across k4 parity-protected; no block barrier needed
    }
}

extern "C" void kernel_launch(void* const* d_in, const int* in_sizes, int n_in,
                              void* d_out, int out_size)
{
    const float* x     = (const float*)d_in[0];
    const float* initp = (const float*)d_in[1];
    const float* W1    = (const float*)d_in[2];
    const float* b1    = (const float*)d_in[3];
    const float* W2    = (const float*)d_in[4];
    const float* b2    = (const float*)d_in[5];
    const float* W3    = (const float*)d_in[6];
    const float* b3    = (const float*)d_in[7];
    float* out = (float*)d_out;

    prepack_kernel<<<32, TPB>>>(W1, b1, W2, b2, W3, b3);
    nsf_ar_kernel<<<NRB * NCH, TPB>>>(x, initp, out);
}